// round 15
// baseline (speedup 1.0000x reference)
#include <cuda_runtime.h>
#include <cuda_bf16.h>
#include <stdint.h>
#include <math.h>

typedef unsigned long long u64;

#define BATCH 4
#define CH 512
#define GH 64
#define GW 64
#define KA 9
#define NPIX (GH*GW)            // 4096
#define NANCH (NPIX*KA)         // 36864
#define PRE 2000
#define PREPAD 2048
#define POST 300
#define IMG_WF 1024.0f
#define IMG_HF 1024.0f
#define BBOX_CLAMP_F 4.135166556742356f

// ---- packed fp32x2 helpers ----
__device__ __forceinline__ void ffma2(u64 &d, u64 a, u64 b) {
    asm("fma.rn.f32x2 %0, %1, %2, %0;" : "+l"(d) : "l"(a), "l"(b));
}
__device__ __forceinline__ u64 pack2(float x, float y) {
    u64 r; asm("mov.b64 %0, {%1, %2};" : "=l"(r) : "f"(x), "f"(y)); return r;
}
__device__ __forceinline__ float2 unpack2(u64 v) {
    float2 r; asm("mov.b64 {%0, %1}, %2;" : "=f"(r.x), "=f"(r.y) : "l"(v)); return r;
}

// ---- device scratch ----
static __device__ float g_featT[(size_t)BATCH*NPIX*CH];
static __device__ float g_wT[(size_t)CH*9*CH];
static __device__ u64   g_keys[BATCH*NANCH];
static __device__ float g_scores[BATCH*NANCH];
static __device__ float g_props[(size_t)BATCH*NANCH*4];
static __device__ float g_boxsel[BATCH*PREPAD*4];
static __device__ float g_scsel[BATCH*PREPAD];
static __device__ unsigned g_small[BATCH*64];
static __device__ unsigned g_mask[(size_t)BATCH*PREPAD*64];
static __device__ unsigned g_keep[BATCH*64];

// ---------------- weight transpose (tiled; values identical) ----------------
__global__ void __launch_bounds__(256) wtrans_kernel(const float* __restrict__ w)
{
    __shared__ float tile[32][33];
    int r0  = blockIdx.x * 32;
    int oc0 = blockIdx.y * 32;
    int tx = threadIdx.x & 31, ty = threadIdx.x >> 5;
#pragma unroll
    for (int k = 0; k < 32; k += 8)
        tile[ty + k][tx] = w[(size_t)(oc0 + ty + k) * (CH*9) + r0 + tx];
    __syncthreads();
#pragma unroll
    for (int k = 0; k < 32; k += 8)
        g_wT[(size_t)(r0 + ty + k) * CH + oc0 + tx] = tile[tx][ty + k];
}

// ---------------- scalar 3x3 conv + ReLU (R4 VERBATIM — do not touch) ----------------
#define ICB 4
__global__ void __launch_bounds__(256) conv3_kernel(const float* __restrict__ fin,
                                                    const float* __restrict__ bias)
{
    __shared__ float s_in[ICB][3][GW+2];
    __shared__ float s_w[ICB*9][128];
    int b = blockIdx.z, y = blockIdx.y;
    int oc0 = blockIdx.x * 128;
    int t = threadIdx.x;
    int tx = t & 7;
    int ty = t >> 3;

    u64 acc2[2][8];
    {
        u64 b01 = pack2(bias[oc0 + ty*4 + 0], bias[oc0 + ty*4 + 1]);
        u64 b23 = pack2(bias[oc0 + ty*4 + 2], bias[oc0 + ty*4 + 3]);
#pragma unroll
        for (int p = 0; p < 8; p++) { acc2[0][p] = b01; acc2[1][p] = b23; }
    }

    for (int ic0 = 0; ic0 < CH; ic0 += ICB) {
        for (int e = t; e < ICB*3*66; e += 256) {
            int ic = e / 198; int r = e % 198; int row = r / 66; int xx = r % 66;
            int gy = y + row - 1; int gx = xx - 1;
            float v = 0.f;
            if ((unsigned)gy < (unsigned)GH && (unsigned)gx < (unsigned)GW)
                v = fin[((size_t)b*CH + ic0 + ic)*NPIX + gy*GW + gx];
            s_in[ic][row][xx] = v;
        }
        const float* wt = g_wT + (size_t)ic0*9*CH + oc0;
        for (int e = t; e < ICB*9*128; e += 256) {
            int rq = e >> 7; int ocl = e & 127;
            s_w[rq][ocl] = wt[(size_t)rq*CH + ocl];
        }
        __syncthreads();
#pragma unroll
        for (int ic = 0; ic < ICB; ic++) {
#pragma unroll
            for (int dy = 0; dy < 3; dy++) {
                u64 xb[10];
#pragma unroll
                for (int u = 0; u < 10; u++) {
                    float vv = s_in[ic][dy][tx*8 + u];
                    xb[u] = pack2(vv, vv);
                }
#pragma unroll
                for (int dx = 0; dx < 3; dx++) {
                    float4 w4 = *(const float4*)&s_w[ic*9 + dy*3 + dx][ty*4];
                    u64 wxy = pack2(w4.x, w4.y);
                    u64 wzw = pack2(w4.z, w4.w);
#pragma unroll
                    for (int p = 0; p < 8; p++) {
                        ffma2(acc2[0][p], wxy, xb[p + dx]);
                        ffma2(acc2[1][p], wzw, xb[p + dx]);
                    }
                }
            }
        }
        __syncthreads();
    }
#pragma unroll
    for (int p = 0; p < 8; p++) {
        int x = tx*8 + p;
        float2 a01 = unpack2(acc2[0][p]);
        float2 a23 = unpack2(acc2[1][p]);
        float4 o = make_float4(fmaxf(a01.x, 0.f), fmaxf(a01.y, 0.f),
                               fmaxf(a23.x, 0.f), fmaxf(a23.y, 0.f));
        *(float4*)&g_featT[((size_t)(b*NPIX + y*GW + x))*CH + oc0 + ty*4] = o;
    }
}

// ---------------- heads: 4 warps per pixel (R13 VERBATIM) ----------------
template<int K0, int K1>
__device__ __forceinline__ void heads_part(int b, int pix, int lane, const float* __restrict__ f,
    const float* __restrict__ wc, const float* __restrict__ bc,
    const float* __restrict__ wb, const float* __restrict__ bbx)
{
    constexpr int NK = K1 - K0;
    u64 accC[NK];
    u64 accB[4*NK];
#pragma unroll
    for (int o = 0; o < NK; o++) accC[o] = 0ull;
#pragma unroll
    for (int o = 0; o < 4*NK; o++) accB[o] = 0ull;
#pragma unroll
    for (int it = 0; it < 4; it++) {
        int c4 = lane + it*32;
        float4 fv = *(const float4*)(f + c4*4);
        u64 fxy = pack2(fv.x, fv.y);
        u64 fzw = pack2(fv.z, fv.w);
#pragma unroll
        for (int o = 0; o < NK; o++) {
            float4 w4 = __ldg((const float4*)(wc + (size_t)(K0 + o)*CH + c4*4));
            ffma2(accC[o], fxy, pack2(w4.x, w4.y));
            ffma2(accC[o], fzw, pack2(w4.z, w4.w));
        }
#pragma unroll
        for (int o = 0; o < 4*NK; o++) {
            float4 w4 = __ldg((const float4*)(wb + (size_t)(4*K0 + o)*CH + c4*4));
            ffma2(accB[o], fxy, pack2(w4.x, w4.y));
            ffma2(accB[o], fzw, pack2(w4.z, w4.w));
        }
    }
    float rc[NK], rb[4*NK];
#pragma unroll
    for (int o = 0; o < NK; o++) {
        float2 h = unpack2(accC[o]);
        float a = h.x + h.y;
#pragma unroll
        for (int s = 16; s > 0; s >>= 1) a += __shfl_xor_sync(0xffffffffu, a, s);
        rc[o] = a;
    }
#pragma unroll
    for (int o = 0; o < 4*NK; o++) {
        float2 h = unpack2(accB[o]);
        float a = h.x + h.y;
#pragma unroll
        for (int s = 16; s > 0; s >>= 1) a += __shfl_xor_sync(0xffffffffu, a, s);
        rb[o] = a;
    }
    if (lane < NK) {
        int k = K0 + lane;
        int y = pix >> 6, x = pix & 63;
        float cls = rc[lane] + bc[k];
        float s = 1.0f / (1.0f + expf(-cls));
        int n = pix*KA + k;
        const float ratios[3] = {0.5f, 1.0f, 2.0f};
        const float scales[3] = {128.0f, 256.0f, 512.0f};
        float hh = sqrtf(ratios[k/3]);
        float ww = 1.0f / hh;
        float ws = ww * scales[k%3];
        float hs = hh * scales[k%3];
        float bx0 = rintf(-ws*0.5f), by0 = rintf(-hs*0.5f);
        float bx2 = rintf( ws*0.5f), by2 = rintf( hs*0.5f);
        float sx = (float)x * 16.0f, sy = (float)y * 16.0f;
        float wa = bx2 - bx0, ha = by2 - by0;
        float cxa = sx + bx0 + 0.5f*wa;
        float cya = sy + by0 + 0.5f*ha;
        float dx = rb[4*lane + 0] + bbx[4*k + 0];
        float dy = rb[4*lane + 1] + bbx[4*k + 1];
        float dw = fminf(rb[4*lane + 2] + bbx[4*k + 2], BBOX_CLAMP_F);
        float dh = fminf(rb[4*lane + 3] + bbx[4*k + 3], BBOX_CLAMP_F);
        float cx = dx * wa + cxa;
        float cy = dy * ha + cya;
        float pw = expf(dw) * wa;
        float ph = expf(dh) * ha;
        float* pr = g_props + ((size_t)b*NANCH + n)*4;
        pr[0] = cx - 0.5f*pw; pr[1] = cy - 0.5f*ph;
        pr[2] = cx + 0.5f*pw; pr[3] = cy + 0.5f*ph;
        unsigned ord = __float_as_uint(s) | 0x80000000u;
        g_keys[b*NANCH + n] = ((u64)(~ord) << 32) | (unsigned)n;
        g_scores[b*NANCH + n] = s;
    }
}

__global__ void __launch_bounds__(256) heads_kernel(
    const float* __restrict__ wc, const float* __restrict__ bc,
    const float* __restrict__ wb, const float* __restrict__ bbx)
{
    int warp = threadIdx.x >> 5, lane = threadIdx.x & 31;
    int pg = blockIdx.x * 2 + (warp >> 2);
    int part = warp & 3;
    int b = pg >> 12;
    int pix = pg & (NPIX - 1);
    const float* f = g_featT + (size_t)pg * CH;
    if      (part == 0) heads_part<0, 2>(b, pix, lane, f, wc, bc, wb, bbx);
    else if (part == 1) heads_part<2, 4>(b, pix, lane, f, wc, bc, wb, bbx);
    else if (part == 2) heads_part<4, 6>(b, pix, lane, f, wc, bc, wb, bbx);
    else                heads_part<6, 9>(b, pix, lane, f, wc, bc, wb, bbx);
}

// ---------------- radix-select: warp-aggregated histogram + parallel scan ----------------
__global__ void __launch_bounds__(1024) select_kernel()
{
    __shared__ u64 skeys[PREPAD];
    __shared__ unsigned cnt[256];
    __shared__ unsigned s_wsum[8];
    __shared__ u64 sh_prefix;
    __shared__ int sh_k;
    __shared__ int sh_cnt;
    __shared__ unsigned ssmall[64];
    int b = blockIdx.x;
    int tid = threadIdx.x;
    int lane = tid & 31;
    const u64* keys = g_keys + (size_t)b*NANCH;

    if (tid == 0) { sh_prefix = 0ull; sh_k = PRE - 1; sh_cnt = 0; }
    if (tid < 64) ssmall[tid] = 0u;
    __syncthreads();

    for (int shift = 56; shift >= 0; shift -= 8) {
        for (int c = tid; c < 256; c += 1024) cnt[c] = 0;
        __syncthreads();
        u64 pfx = sh_prefix;
        int kcur = sh_k;
        for (int i = tid; i < NANCH; i += 1024) {
            u64 key = keys[i];
            bool cond = (shift == 56) || ((key >> (shift+8)) == (pfx >> (shift+8)));
            unsigned bucket = (unsigned)(key >> shift) & 255u;
            unsigned active = __ballot_sync(0xffffffffu, cond);
            if (cond) {
                unsigned peers = __match_any_sync(active, bucket);
                int leader = __ffs(peers) - 1;
                if (lane == leader)
                    atomicAdd(&cnt[bucket], (unsigned)__popc(peers));
            }
        }
        __syncthreads();
        if (tid < 256) {
            unsigned c = cnt[tid];
            unsigned v = c;
#pragma unroll
            for (int o = 1; o < 32; o <<= 1) {
                unsigned n = __shfl_up_sync(0xffffffffu, v, o);
                if ((tid & 31) >= o) v += n;
            }
            if ((tid & 31) == 31) s_wsum[tid >> 5] = v;
            __syncwarp();
            cnt[tid] = c;
            skeys[tid] = v;
        }
        __syncthreads();
        if (tid < 8) {
            unsigned w = s_wsum[tid];
#pragma unroll
            for (int o = 1; o < 8; o <<= 1) {
                unsigned n = __shfl_up_sync(0x000000ffu, w, o);
                if (tid >= o) w += n;
            }
            s_wsum[tid] = w;
        }
        __syncthreads();
        if (tid < 256) {
            unsigned incl = (unsigned)skeys[tid] + ((tid >= 32) ? s_wsum[(tid >> 5) - 1] : 0u);
            unsigned c = cnt[tid];
            unsigned excl = incl - c;
            if (c > 0 && excl <= (unsigned)kcur && (unsigned)kcur < excl + c) {
                sh_prefix = pfx | ((u64)(unsigned)tid << shift);
                sh_k = kcur - (int)excl;
            }
        }
        __syncthreads();
    }
    u64 T = sh_prefix;

    // warp-aggregated compaction (placement order irrelevant: sorted below)
    for (int i = tid; i < NANCH; i += 1024) {
        u64 key = keys[i];
        bool pred = (key <= T);
        unsigned mask = __ballot_sync(0xffffffffu, pred);
        if (pred) {
            int leader = __ffs(mask) - 1;
            int rank = __popc(mask & ((1u << lane) - 1u));
            int base = 0;
            if (lane == leader) base = atomicAdd(&sh_cnt, __popc(mask));
            base = __shfl_sync(mask, base, leader);
            skeys[base + rank] = key;
        }
    }
    __syncthreads();
    for (int p = PRE + tid; p < PREPAD; p += 1024) skeys[p] = 0xFFFFFFFFFFFFFFFFull;
    __syncthreads();

    for (int k = 2; k <= PREPAD; k <<= 1) {
        for (int j = k >> 1; j > 0; j >>= 1) {
            for (int i = tid; i < PREPAD; i += 1024) {
                int ixj = i ^ j;
                if (ixj > i) {
                    bool up = ((i & k) == 0);
                    u64 a = skeys[i], c = skeys[ixj];
                    if ((a > c) == up) { skeys[i] = c; skeys[ixj] = a; }
                }
            }
            __syncthreads();
        }
    }

    for (int s = tid; s < PREPAD; s += 1024) {
        u64 key = skeys[s];
        bool valid = (s < PRE);
        float x1=0.f, y1=0.f, x2=0.f, y2=0.f, sc = -INFINITY;
        if (valid) {
            unsigned idx = (unsigned)(key & 0xFFFFFFFFull);
            const float* pr = g_props + ((size_t)b*NANCH + idx)*4;
            x1 = fminf(fmaxf(pr[0], 0.f), IMG_WF);
            y1 = fminf(fmaxf(pr[1], 0.f), IMG_HF);
            x2 = fminf(fmaxf(pr[2], 0.f), IMG_WF);
            y2 = fminf(fmaxf(pr[3], 0.f), IMG_HF);
            sc = g_scores[b*NANCH + idx];
        }
        bool small = ((x2 - x1) < 16.0f) || ((y2 - y1) < 16.0f);
        if (valid && small) sc = -INFINITY;
        if (!valid || small) atomicOr(&ssmall[s >> 5], 1u << (s & 31));
        float* bo = g_boxsel + ((size_t)b*PREPAD + s)*4;
        bo[0]=x1; bo[1]=y1; bo[2]=x2; bo[3]=y2;
        g_scsel[b*PREPAD + s] = sc;
    }
    __syncthreads();
    if (tid < 64) g_small[b*64 + tid] = ssmall[tid];
}

// ---------------- IoU suppression bitmask (R4 shape) ----------------
__global__ void __launch_bounds__(64) nms_mask_kernel()
{
    int i = blockIdx.x, b = blockIdx.y;
    int w = threadIdx.x;
    unsigned m = 0;
    if (i < PRE) {
        const float* bi = g_boxsel + ((size_t)b*PREPAD + i)*4;
        float ax1 = bi[0], ay1 = bi[1], ax2 = bi[2], ay2 = bi[3];
        float aarea = (ax2 - ax1) * (ay2 - ay1);
        const float* base = g_boxsel + (size_t)b*PREPAD*4;
#pragma unroll 4
        for (int t = 0; t < 32; t++) {
            int j = w*32 + t;
            if (j > i && j < PRE) {
                const float* bj = base + (size_t)j*4;
                float bx1 = bj[0], by1 = bj[1], bx2 = bj[2], by2 = bj[3];
                float barea = (bx2 - bx1) * (by2 - by1);
                float lx = fmaxf(ax1, bx1), ly = fmaxf(ay1, by1);
                float rx = fminf(ax2, bx2), ry = fminf(ay2, by2);
                float iw = fmaxf(rx - lx, 0.f), ih = fmaxf(ry - ly, 0.f);
                float inter = iw * ih;
                float iou = inter / (aarea + barea - inter);
                if (iou > 0.7f) m |= (1u << t);
            }
        }
    }
    g_mask[((size_t)b*PREPAD + i)*64 + w] = m;
}

// ---------------- serial NMS scan ----------------
__global__ void __launch_bounds__(32) nms_scan_kernel()
{
    int b = blockIdx.x;
    int lane = threadIdx.x;
    unsigned remv0 = g_small[b*64 + lane];
    unsigned remv1 = g_small[b*64 + 32 + lane];
    unsigned keep0 = 0, keep1 = 0;
    const unsigned* maskb = g_mask + (size_t)b*PREPAD*64;
    unsigned m0 = maskb[lane], m1 = maskb[32 + lane];
    for (int i = 0; i < PRE; i++) {
        unsigned nm0 = 0, nm1 = 0;
        if (i + 1 < PRE) {
            nm0 = maskb[(size_t)(i+1)*64 + lane];
            nm1 = maskb[(size_t)(i+1)*64 + 32 + lane];
        }
        int w = i >> 5;
        unsigned myword = (w < 32) ? remv0 : remv1;
        unsigned word = __shfl_sync(0xffffffffu, myword, w & 31);
        bool sup = (word >> (i & 31)) & 1u;
        if (!sup) {
            if (lane == (w & 31)) {
                if (w < 32) keep0 |= 1u << (i & 31);
                else        keep1 |= 1u << (i & 31);
            }
            remv0 |= m0; remv1 |= m1;
        }
        m0 = nm0; m1 = nm1;
    }
    g_keep[b*64 + lane] = keep0;
    g_keep[b*64 + 32 + lane] = keep1;
}

// ---------------- stable partition, take 300 ----------------
__global__ void __launch_bounds__(256) finalize_kernel(float* __restrict__ out)
{
    __shared__ unsigned kw[64];
    __shared__ int base[65];
    int b = blockIdx.x, tid = threadIdx.x;
    if (tid < 64) kw[tid] = g_keep[b*64 + tid];
    __syncthreads();
    if (tid == 0) {
        int run = 0;
        for (int w = 0; w < 64; w++) { base[w] = run; run += __popc(kw[w]); }
        base[64] = run;
    }
    __syncthreads();
    int nkept = base[64];
    for (int i = tid; i < PRE; i += 256) {
        int w = i >> 5, bit = i & 31;
        int keptpre = base[w] + __popc(kw[w] & ((1u << bit) - 1u));
        bool kp = (kw[w] >> bit) & 1u;
        int pos = kp ? keptpre : (nkept + (i - keptpre));
        if (pos < POST) {
            const float* bo = g_boxsel + ((size_t)b*PREPAD + i)*4;
            float* po = out + (size_t)b*POST*4 + (size_t)pos*4;
            po[0] = bo[0]; po[1] = bo[1]; po[2] = bo[2]; po[3] = bo[3];
            out[(size_t)BATCH*POST*4 + b*POST + pos] = kp ? g_scsel[b*PREPAD + i] : -INFINITY;
        }
    }
}

extern "C" void kernel_launch(void* const* d_in, const int* in_sizes, int n_in,
                              void* d_out, int out_size)
{
    const float* feature = (const float*)d_in[1];
    const float* w_conv  = (const float*)d_in[2];
    const float* b_conv  = (const float*)d_in[3];
    const float* w_cls   = (const float*)d_in[4];
    const float* b_cls   = (const float*)d_in[5];
    const float* w_box   = (const float*)d_in[6];
    const float* b_box   = (const float*)d_in[7];
    float* out = (float*)d_out;

    wtrans_kernel<<<dim3((CH*9)/32, CH/32), 256>>>(w_conv);
    conv3_kernel<<<dim3(4, GH, BATCH), 256>>>(feature, b_conv);
    heads_kernel<<<BATCH*NPIX/2, 256>>>(w_cls, b_cls, w_box, b_box);
    select_kernel<<<BATCH, 1024>>>();
    nms_mask_kernel<<<dim3(PREPAD, BATCH), 64>>>();
    nms_scan_kernel<<<BATCH, 32>>>();
    finalize_kernel<<<BATCH, 256>>>(out);
}

// round 16
// speedup vs baseline: 1.0216x; 1.0216x over previous
#include <cuda_runtime.h>
#include <cuda_bf16.h>
#include <stdint.h>
#include <math.h>

typedef unsigned long long u64;

#define BATCH 4
#define CH 512
#define GH 64
#define GW 64
#define KA 9
#define NPIX (GH*GW)            // 4096
#define NANCH (NPIX*KA)         // 36864
#define PRE 2000
#define PREPAD 2048
#define POST 300
#define IMG_WF 1024.0f
#define IMG_HF 1024.0f
#define BBOX_CLAMP_F 4.135166556742356f

// ---- packed fp32x2 helpers ----
__device__ __forceinline__ void ffma2(u64 &d, u64 a, u64 b) {
    asm("fma.rn.f32x2 %0, %1, %2, %0;" : "+l"(d) : "l"(a), "l"(b));
}
__device__ __forceinline__ u64 pack2(float x, float y) {
    u64 r; asm("mov.b64 %0, {%1, %2};" : "=l"(r) : "f"(x), "f"(y)); return r;
}
__device__ __forceinline__ float2 unpack2(u64 v) {
    float2 r; asm("mov.b64 {%0, %1}, %2;" : "=f"(r.x), "=f"(r.y) : "l"(v)); return r;
}

// ---- device scratch ----
static __device__ float g_featT[(size_t)BATCH*NPIX*CH];
static __device__ float g_wT[(size_t)CH*9*CH];
static __device__ u64   g_keys[BATCH*NANCH];
static __device__ float g_scores[BATCH*NANCH];
static __device__ float g_props[(size_t)BATCH*NANCH*4];
static __device__ float g_boxsel[BATCH*PREPAD*4];
static __device__ float g_scsel[BATCH*PREPAD];
static __device__ unsigned g_small[BATCH*64];
static __device__ unsigned g_mask[(size_t)BATCH*PREPAD*64];
static __device__ unsigned g_keep[BATCH*64];

// ---------------- weight transpose (tiled; values identical) ----------------
__global__ void __launch_bounds__(256) wtrans_kernel(const float* __restrict__ w)
{
    __shared__ float tile[32][33];
    int r0  = blockIdx.x * 32;
    int oc0 = blockIdx.y * 32;
    int tx = threadIdx.x & 31, ty = threadIdx.x >> 5;
#pragma unroll
    for (int k = 0; k < 32; k += 8)
        tile[ty + k][tx] = w[(size_t)(oc0 + ty + k) * (CH*9) + r0 + tx];
    __syncthreads();
#pragma unroll
    for (int k = 0; k < 32; k += 8)
        g_wT[(size_t)(r0 + ty + k) * CH + oc0 + tx] = tile[tx][ty + k];
}

// ---------------- scalar 3x3 conv + ReLU (R4 VERBATIM — do not touch) ----------------
#define ICB 4
__global__ void __launch_bounds__(256) conv3_kernel(const float* __restrict__ fin,
                                                    const float* __restrict__ bias)
{
    __shared__ float s_in[ICB][3][GW+2];
    __shared__ float s_w[ICB*9][128];
    int b = blockIdx.z, y = blockIdx.y;
    int oc0 = blockIdx.x * 128;
    int t = threadIdx.x;
    int tx = t & 7;
    int ty = t >> 3;

    u64 acc2[2][8];
    {
        u64 b01 = pack2(bias[oc0 + ty*4 + 0], bias[oc0 + ty*4 + 1]);
        u64 b23 = pack2(bias[oc0 + ty*4 + 2], bias[oc0 + ty*4 + 3]);
#pragma unroll
        for (int p = 0; p < 8; p++) { acc2[0][p] = b01; acc2[1][p] = b23; }
    }

    for (int ic0 = 0; ic0 < CH; ic0 += ICB) {
        for (int e = t; e < ICB*3*66; e += 256) {
            int ic = e / 198; int r = e % 198; int row = r / 66; int xx = r % 66;
            int gy = y + row - 1; int gx = xx - 1;
            float v = 0.f;
            if ((unsigned)gy < (unsigned)GH && (unsigned)gx < (unsigned)GW)
                v = fin[((size_t)b*CH + ic0 + ic)*NPIX + gy*GW + gx];
            s_in[ic][row][xx] = v;
        }
        const float* wt = g_wT + (size_t)ic0*9*CH + oc0;
        for (int e = t; e < ICB*9*128; e += 256) {
            int rq = e >> 7; int ocl = e & 127;
            s_w[rq][ocl] = wt[(size_t)rq*CH + ocl];
        }
        __syncthreads();
#pragma unroll
        for (int ic = 0; ic < ICB; ic++) {
#pragma unroll
            for (int dy = 0; dy < 3; dy++) {
                u64 xb[10];
#pragma unroll
                for (int u = 0; u < 10; u++) {
                    float vv = s_in[ic][dy][tx*8 + u];
                    xb[u] = pack2(vv, vv);
                }
#pragma unroll
                for (int dx = 0; dx < 3; dx++) {
                    float4 w4 = *(const float4*)&s_w[ic*9 + dy*3 + dx][ty*4];
                    u64 wxy = pack2(w4.x, w4.y);
                    u64 wzw = pack2(w4.z, w4.w);
#pragma unroll
                    for (int p = 0; p < 8; p++) {
                        ffma2(acc2[0][p], wxy, xb[p + dx]);
                        ffma2(acc2[1][p], wzw, xb[p + dx]);
                    }
                }
            }
        }
        __syncthreads();
    }
#pragma unroll
    for (int p = 0; p < 8; p++) {
        int x = tx*8 + p;
        float2 a01 = unpack2(acc2[0][p]);
        float2 a23 = unpack2(acc2[1][p]);
        float4 o = make_float4(fmaxf(a01.x, 0.f), fmaxf(a01.y, 0.f),
                               fmaxf(a23.x, 0.f), fmaxf(a23.y, 0.f));
        *(float4*)&g_featT[((size_t)(b*NPIX + y*GW + x))*CH + oc0 + ty*4] = o;
    }
}

// ---------------- heads: 4 warps per pixel (R13 VERBATIM) ----------------
template<int K0, int K1>
__device__ __forceinline__ void heads_part(int b, int pix, int lane, const float* __restrict__ f,
    const float* __restrict__ wc, const float* __restrict__ bc,
    const float* __restrict__ wb, const float* __restrict__ bbx)
{
    constexpr int NK = K1 - K0;
    u64 accC[NK];
    u64 accB[4*NK];
#pragma unroll
    for (int o = 0; o < NK; o++) accC[o] = 0ull;
#pragma unroll
    for (int o = 0; o < 4*NK; o++) accB[o] = 0ull;
#pragma unroll
    for (int it = 0; it < 4; it++) {
        int c4 = lane + it*32;
        float4 fv = *(const float4*)(f + c4*4);
        u64 fxy = pack2(fv.x, fv.y);
        u64 fzw = pack2(fv.z, fv.w);
#pragma unroll
        for (int o = 0; o < NK; o++) {
            float4 w4 = __ldg((const float4*)(wc + (size_t)(K0 + o)*CH + c4*4));
            ffma2(accC[o], fxy, pack2(w4.x, w4.y));
            ffma2(accC[o], fzw, pack2(w4.z, w4.w));
        }
#pragma unroll
        for (int o = 0; o < 4*NK; o++) {
            float4 w4 = __ldg((const float4*)(wb + (size_t)(4*K0 + o)*CH + c4*4));
            ffma2(accB[o], fxy, pack2(w4.x, w4.y));
            ffma2(accB[o], fzw, pack2(w4.z, w4.w));
        }
    }
    float rc[NK], rb[4*NK];
#pragma unroll
    for (int o = 0; o < NK; o++) {
        float2 h = unpack2(accC[o]);
        float a = h.x + h.y;
#pragma unroll
        for (int s = 16; s > 0; s >>= 1) a += __shfl_xor_sync(0xffffffffu, a, s);
        rc[o] = a;
    }
#pragma unroll
    for (int o = 0; o < 4*NK; o++) {
        float2 h = unpack2(accB[o]);
        float a = h.x + h.y;
#pragma unroll
        for (int s = 16; s > 0; s >>= 1) a += __shfl_xor_sync(0xffffffffu, a, s);
        rb[o] = a;
    }
    if (lane < NK) {
        int k = K0 + lane;
        int y = pix >> 6, x = pix & 63;
        float cls = rc[lane] + bc[k];
        float s = 1.0f / (1.0f + expf(-cls));
        int n = pix*KA + k;
        const float ratios[3] = {0.5f, 1.0f, 2.0f};
        const float scales[3] = {128.0f, 256.0f, 512.0f};
        float hh = sqrtf(ratios[k/3]);
        float ww = 1.0f / hh;
        float ws = ww * scales[k%3];
        float hs = hh * scales[k%3];
        float bx0 = rintf(-ws*0.5f), by0 = rintf(-hs*0.5f);
        float bx2 = rintf( ws*0.5f), by2 = rintf( hs*0.5f);
        float sx = (float)x * 16.0f, sy = (float)y * 16.0f;
        float wa = bx2 - bx0, ha = by2 - by0;
        float cxa = sx + bx0 + 0.5f*wa;
        float cya = sy + by0 + 0.5f*ha;
        float dx = rb[4*lane + 0] + bbx[4*k + 0];
        float dy = rb[4*lane + 1] + bbx[4*k + 1];
        float dw = fminf(rb[4*lane + 2] + bbx[4*k + 2], BBOX_CLAMP_F);
        float dh = fminf(rb[4*lane + 3] + bbx[4*k + 3], BBOX_CLAMP_F);
        float cx = dx * wa + cxa;
        float cy = dy * ha + cya;
        float pw = expf(dw) * wa;
        float ph = expf(dh) * ha;
        float* pr = g_props + ((size_t)b*NANCH + n)*4;
        pr[0] = cx - 0.5f*pw; pr[1] = cy - 0.5f*ph;
        pr[2] = cx + 0.5f*pw; pr[3] = cy + 0.5f*ph;
        unsigned ord = __float_as_uint(s) | 0x80000000u;
        g_keys[b*NANCH + n] = ((u64)(~ord) << 32) | (unsigned)n;
        g_scores[b*NANCH + n] = s;
    }
}

__global__ void __launch_bounds__(256) heads_kernel(
    const float* __restrict__ wc, const float* __restrict__ bc,
    const float* __restrict__ wb, const float* __restrict__ bbx)
{
    int warp = threadIdx.x >> 5, lane = threadIdx.x & 31;
    int pg = blockIdx.x * 2 + (warp >> 2);
    int part = warp & 3;
    int b = pg >> 12;
    int pix = pg & (NPIX - 1);
    const float* f = g_featT + (size_t)pg * CH;
    if      (part == 0) heads_part<0, 2>(b, pix, lane, f, wc, bc, wb, bbx);
    else if (part == 1) heads_part<2, 4>(b, pix, lane, f, wc, bc, wb, bbx);
    else if (part == 2) heads_part<4, 6>(b, pix, lane, f, wc, bc, wb, bbx);
    else                heads_part<6, 9>(b, pix, lane, f, wc, bc, wb, bbx);
}

// ---------------- radix-select: per-warp privatized histograms ----------------
// dynamic smem: skeys[PREPAD] (16KB) then hist[32*256] (32KB)
__global__ void __launch_bounds__(1024) select_kernel()
{
    extern __shared__ __align__(16) char dyn[];
    u64* skeys = (u64*)dyn;                               // PREPAD u64
    unsigned* hist = (unsigned*)(dyn + PREPAD*8);         // 32*256
    __shared__ unsigned cnt[256];
    __shared__ unsigned s_wsum[8];
    __shared__ u64 sh_prefix;
    __shared__ int sh_k;
    __shared__ int sh_cnt;
    __shared__ unsigned ssmall[64];
    int b = blockIdx.x;
    int tid = threadIdx.x;
    int warp = tid >> 5;
    const u64* keys = g_keys + (size_t)b*NANCH;

    if (tid == 0) { sh_prefix = 0ull; sh_k = PRE - 1; sh_cnt = 0; }
    if (tid < 64) ssmall[tid] = 0u;
    __syncthreads();

    for (int shift = 56; shift >= 0; shift -= 8) {
        for (int c = tid; c < 32*256; c += 1024) hist[c] = 0;
        __syncthreads();
        u64 pfx = sh_prefix;
        int kcur = sh_k;
        unsigned* myh = hist + warp*256;
        for (int i = tid; i < NANCH; i += 1024) {
            u64 key = keys[i];
            bool cond = (shift == 56) || ((key >> (shift+8)) == (pfx >> (shift+8)));
            if (cond) atomicAdd(&myh[(unsigned)(key >> shift) & 255u], 1u);
        }
        __syncthreads();
        // reduce 32 private copies, then parallel prefix scan over 256 buckets
        if (tid < 256) {
            unsigned c = 0;
#pragma unroll
            for (int w = 0; w < 32; w++) c += hist[w*256 + tid];
            cnt[tid] = c;
            unsigned v = c;
#pragma unroll
            for (int o = 1; o < 32; o <<= 1) {
                unsigned n = __shfl_up_sync(0xffffffffu, v, o);
                if ((tid & 31) >= o) v += n;
            }
            if ((tid & 31) == 31) s_wsum[tid >> 5] = v;
            __syncwarp();
            skeys[tid] = v;       // scratch: within-warp inclusive
        }
        __syncthreads();
        if (tid < 8) {
            unsigned w = s_wsum[tid];
#pragma unroll
            for (int o = 1; o < 8; o <<= 1) {
                unsigned n = __shfl_up_sync(0x000000ffu, w, o);
                if (tid >= o) w += n;
            }
            s_wsum[tid] = w;
        }
        __syncthreads();
        if (tid < 256) {
            unsigned incl = (unsigned)skeys[tid] + ((tid >= 32) ? s_wsum[(tid >> 5) - 1] : 0u);
            unsigned c = cnt[tid];
            unsigned excl = incl - c;
            if (c > 0 && excl <= (unsigned)kcur && (unsigned)kcur < excl + c) {
                sh_prefix = pfx | ((u64)(unsigned)tid << shift);
                sh_k = kcur - (int)excl;
            }
        }
        __syncthreads();
    }
    u64 T = sh_prefix;   // exact rank-1999 key (keys unique)

    for (int i = tid; i < NANCH; i += 1024) {
        u64 key = keys[i];
        if (key <= T) {
            int p = atomicAdd(&sh_cnt, 1);
            skeys[p] = key;
        }
    }
    __syncthreads();
    for (int p = PRE + tid; p < PREPAD; p += 1024) skeys[p] = 0xFFFFFFFFFFFFFFFFull;
    __syncthreads();

    for (int k = 2; k <= PREPAD; k <<= 1) {
        for (int j = k >> 1; j > 0; j >>= 1) {
            for (int i = tid; i < PREPAD; i += 1024) {
                int ixj = i ^ j;
                if (ixj > i) {
                    bool up = ((i & k) == 0);
                    u64 a = skeys[i], c = skeys[ixj];
                    if ((a > c) == up) { skeys[i] = c; skeys[ixj] = a; }
                }
            }
            __syncthreads();
        }
    }

    for (int s = tid; s < PREPAD; s += 1024) {
        u64 key = skeys[s];
        bool valid = (s < PRE);
        float x1=0.f, y1=0.f, x2=0.f, y2=0.f, sc = -INFINITY;
        if (valid) {
            unsigned idx = (unsigned)(key & 0xFFFFFFFFull);
            const float* pr = g_props + ((size_t)b*NANCH + idx)*4;
            x1 = fminf(fmaxf(pr[0], 0.f), IMG_WF);
            y1 = fminf(fmaxf(pr[1], 0.f), IMG_HF);
            x2 = fminf(fmaxf(pr[2], 0.f), IMG_WF);
            y2 = fminf(fmaxf(pr[3], 0.f), IMG_HF);
            sc = g_scores[b*NANCH + idx];
        }
        bool small = ((x2 - x1) < 16.0f) || ((y2 - y1) < 16.0f);
        if (valid && small) sc = -INFINITY;
        if (!valid || small) atomicOr(&ssmall[s >> 5], 1u << (s & 31));
        float* bo = g_boxsel + ((size_t)b*PREPAD + s)*4;
        bo[0]=x1; bo[1]=y1; bo[2]=x2; bo[3]=y2;
        g_scsel[b*PREPAD + s] = sc;
    }
    __syncthreads();
    if (tid < 64) g_small[b*64 + tid] = ssmall[tid];
}

// ---------------- IoU suppression bitmask (R4 shape) ----------------
__global__ void __launch_bounds__(64) nms_mask_kernel()
{
    int i = blockIdx.x, b = blockIdx.y;
    int w = threadIdx.x;
    unsigned m = 0;
    if (i < PRE) {
        const float* bi = g_boxsel + ((size_t)b*PREPAD + i)*4;
        float ax1 = bi[0], ay1 = bi[1], ax2 = bi[2], ay2 = bi[3];
        float aarea = (ax2 - ax1) * (ay2 - ay1);
        const float* base = g_boxsel + (size_t)b*PREPAD*4;
#pragma unroll 4
        for (int t = 0; t < 32; t++) {
            int j = w*32 + t;
            if (j > i && j < PRE) {
                const float* bj = base + (size_t)j*4;
                float bx1 = bj[0], by1 = bj[1], bx2 = bj[2], by2 = bj[3];
                float barea = (bx2 - bx1) * (by2 - by1);
                float lx = fmaxf(ax1, bx1), ly = fmaxf(ay1, by1);
                float rx = fminf(ax2, bx2), ry = fminf(ay2, by2);
                float iw = fmaxf(rx - lx, 0.f), ih = fmaxf(ry - ly, 0.f);
                float inter = iw * ih;
                float iou = inter / (aarea + barea - inter);
                if (iou > 0.7f) m |= (1u << t);
            }
        }
    }
    g_mask[((size_t)b*PREPAD + i)*64 + w] = m;
}

// ---------------- serial NMS scan ----------------
__global__ void __launch_bounds__(32) nms_scan_kernel()
{
    int b = blockIdx.x;
    int lane = threadIdx.x;
    unsigned remv0 = g_small[b*64 + lane];
    unsigned remv1 = g_small[b*64 + 32 + lane];
    unsigned keep0 = 0, keep1 = 0;
    const unsigned* maskb = g_mask + (size_t)b*PREPAD*64;
    unsigned m0 = maskb[lane], m1 = maskb[32 + lane];
    for (int i = 0; i < PRE; i++) {
        unsigned nm0 = 0, nm1 = 0;
        if (i + 1 < PRE) {
            nm0 = maskb[(size_t)(i+1)*64 + lane];
            nm1 = maskb[(size_t)(i+1)*64 + 32 + lane];
        }
        int w = i >> 5;
        unsigned myword = (w < 32) ? remv0 : remv1;
        unsigned word = __shfl_sync(0xffffffffu, myword, w & 31);
        bool sup = (word >> (i & 31)) & 1u;
        if (!sup) {
            if (lane == (w & 31)) {
                if (w < 32) keep0 |= 1u << (i & 31);
                else        keep1 |= 1u << (i & 31);
            }
            remv0 |= m0; remv1 |= m1;
        }
        m0 = nm0; m1 = nm1;
    }
    g_keep[b*64 + lane] = keep0;
    g_keep[b*64 + 32 + lane] = keep1;
}

// ---------------- stable partition, take 300 ----------------
__global__ void __launch_bounds__(256) finalize_kernel(float* __restrict__ out)
{
    __shared__ unsigned kw[64];
    __shared__ int base[65];
    int b = blockIdx.x, tid = threadIdx.x;
    if (tid < 64) kw[tid] = g_keep[b*64 + tid];
    __syncthreads();
    if (tid == 0) {
        int run = 0;
        for (int w = 0; w < 64; w++) { base[w] = run; run += __popc(kw[w]); }
        base[64] = run;
    }
    __syncthreads();
    int nkept = base[64];
    for (int i = tid; i < PRE; i += 256) {
        int w = i >> 5, bit = i & 31;
        int keptpre = base[w] + __popc(kw[w] & ((1u << bit) - 1u));
        bool kp = (kw[w] >> bit) & 1u;
        int pos = kp ? keptpre : (nkept + (i - keptpre));
        if (pos < POST) {
            const float* bo = g_boxsel + ((size_t)b*PREPAD + i)*4;
            float* po = out + (size_t)b*POST*4 + (size_t)pos*4;
            po[0] = bo[0]; po[1] = bo[1]; po[2] = bo[2]; po[3] = bo[3];
            out[(size_t)BATCH*POST*4 + b*POST + pos] = kp ? g_scsel[b*PREPAD + i] : -INFINITY;
        }
    }
}

extern "C" void kernel_launch(void* const* d_in, const int* in_sizes, int n_in,
                              void* d_out, int out_size)
{
    const float* feature = (const float*)d_in[1];
    const float* w_conv  = (const float*)d_in[2];
    const float* b_conv  = (const float*)d_in[3];
    const float* w_cls   = (const float*)d_in[4];
    const float* b_cls   = (const float*)d_in[5];
    const float* w_box   = (const float*)d_in[6];
    const float* b_box   = (const float*)d_in[7];
    float* out = (float*)d_out;

    cudaFuncSetAttribute(select_kernel, cudaFuncAttributeMaxDynamicSharedMemorySize, PREPAD*8 + 32*256*4);

    wtrans_kernel<<<dim3((CH*9)/32, CH/32), 256>>>(w_conv);
    conv3_kernel<<<dim3(4, GH, BATCH), 256>>>(feature, b_conv);
    heads_kernel<<<BATCH*NPIX/2, 256>>>(w_cls, b_cls, w_box, b_box);
    select_kernel<<<BATCH, 1024, PREPAD*8 + 32*256*4>>>();
    nms_mask_kernel<<<dim3(PREPAD, BATCH), 64>>>();
    nms_scan_kernel<<<BATCH, 32>>>();
    finalize_kernel<<<BATCH, 256>>>(out);
}